// round 4
// baseline (speedup 1.0000x reference)
#include <cuda_runtime.h>

// ---------------------------------------------------------------------------
// Fused 2-layer LSTM (H=50, D=1) + final FC, batch=2048, T=512, fp32.
//
// Parallelization: batch is fully independent -> persistent blocks, one per
// SM (grid=147). Each block owns 14 batches and runs the whole T=512 loop
// with only __syncthreads() between the per-step layer stages. Each thread
// owns one (batch-pair, hidden-unit): computes the 4 gate rows for its
// hidden unit for 2 batches, keeping cell state c in registers.
//
// Weights live in shared memory in a gate-interleaved float4 layout
// W[k][hid] = {w_i, w_f, w_g, w_o} so the inner dot loop is:
//     1x LDS.128 (weights) + 1x LDS.64 (h pair) + 8x FFMA   per k.
// ---------------------------------------------------------------------------

#define HN      50
#define TN      512
#define BATCHN  2048
#define NB      14          // batches per block
#define NPAIR   7           // batch pairs per block
#define NTHREADS (NPAIR * HN)   // 350
#define NGRID   ((BATCHN + NB - 1) / NB)   // 147

struct Smem {
    float4 w0 [HN * HN];   // [k][hid] gates of W_hh0
    float4 wi1[HN * HN];   // [k][hid] gates of W_ih1
    float4 w1 [HN * HN];   // [k][hid] gates of W_hh1
    float4 bias0[HN];      // b_ih0 + b_hh0, per gate
    float4 bias1[HN];      // b_ih1 + b_hh1, per gate
    float4 wx0[HN];        // W_ih0[:,0], per gate (D == 1)
    float  h0buf[2][HN][NB];
    float  h1buf[2][HN][NB];
    float  wfc[2 * HN];
    float  bfc2[2];
};

__device__ __forceinline__ float sig_f(float v) {
    return __fdividef(1.0f, 1.0f + __expf(-v));
}
__device__ __forceinline__ float tanh_f(float v) {
    // 1 - 2/(1+e^{2v}); __fdividef(2, inf) -> 0 so large |v| saturates cleanly
    return 1.0f - __fdividef(2.0f, 1.0f + __expf(2.0f * v));
}

__global__ __launch_bounds__(NTHREADS, 1)
void lstm_fused_kernel(const float* __restrict__ x,      // [B,T,1]
                       const float* __restrict__ Wih0,   // [200,1]
                       const float* __restrict__ Whh0,   // [200,50]
                       const float* __restrict__ bih0,   // [200]
                       const float* __restrict__ bhh0,   // [200]
                       const float* __restrict__ Wih1,   // [200,50]
                       const float* __restrict__ Whh1,   // [200,50]
                       const float* __restrict__ bih1,   // [200]
                       const float* __restrict__ bhh1,   // [200]
                       const float* __restrict__ Wfc,    // [2,50]
                       const float* __restrict__ bfc,    // [2]
                       float* __restrict__ out)          // [B,2]
{
    extern __shared__ char smem_raw[];
    Smem* s = reinterpret_cast<Smem*>(smem_raw);
    const int tid = threadIdx.x;

    // ---------------- stage weights into shared (once per block) ----------
    for (int idx = tid; idx < HN * HN; idx += NTHREADS) {
        const int k = idx / HN, hid = idx % HN;
        s->w0[idx] = make_float4(Whh0[(0 * HN + hid) * HN + k],
                                 Whh0[(1 * HN + hid) * HN + k],
                                 Whh0[(2 * HN + hid) * HN + k],
                                 Whh0[(3 * HN + hid) * HN + k]);
        s->wi1[idx] = make_float4(Wih1[(0 * HN + hid) * HN + k],
                                  Wih1[(1 * HN + hid) * HN + k],
                                  Wih1[(2 * HN + hid) * HN + k],
                                  Wih1[(3 * HN + hid) * HN + k]);
        s->w1[idx] = make_float4(Whh1[(0 * HN + hid) * HN + k],
                                 Whh1[(1 * HN + hid) * HN + k],
                                 Whh1[(2 * HN + hid) * HN + k],
                                 Whh1[(3 * HN + hid) * HN + k]);
    }
    for (int hid = tid; hid < HN; hid += NTHREADS) {
        s->bias0[hid] = make_float4(bih0[0 * HN + hid] + bhh0[0 * HN + hid],
                                    bih0[1 * HN + hid] + bhh0[1 * HN + hid],
                                    bih0[2 * HN + hid] + bhh0[2 * HN + hid],
                                    bih0[3 * HN + hid] + bhh0[3 * HN + hid]);
        s->bias1[hid] = make_float4(bih1[0 * HN + hid] + bhh1[0 * HN + hid],
                                    bih1[1 * HN + hid] + bhh1[1 * HN + hid],
                                    bih1[2 * HN + hid] + bhh1[2 * HN + hid],
                                    bih1[3 * HN + hid] + bhh1[3 * HN + hid]);
        s->wx0[hid] = make_float4(Wih0[0 * HN + hid], Wih0[1 * HN + hid],
                                  Wih0[2 * HN + hid], Wih0[3 * HN + hid]);
    }
    for (int i = tid; i < 2 * HN; i += NTHREADS) s->wfc[i] = Wfc[i];
    if (tid < 2) s->bfc2[tid] = bfc[tid];
    // zero initial hidden state (buffer 0 is read at t=0)
    for (int i = tid; i < HN * NB; i += NTHREADS) {
        (&s->h0buf[0][0][0])[i] = 0.0f;
        (&s->h1buf[0][0][0])[i] = 0.0f;
    }
    __syncthreads();

    // ---------------- per-thread identity ---------------------------------
    const int hid = tid / NPAIR;       // hidden unit owned by this thread
    const int pr  = tid % NPAIR;       // batch pair within block
    const int b0  = blockIdx.x * NB + pr * 2;
    const int b1  = b0 + 1;
    const long xo0 = (long)(b0 < BATCHN ? b0 : BATCHN - 1) * TN;
    const long xo1 = (long)(b1 < BATCHN ? b1 : BATCHN - 1) * TN;

    // loop-invariant per-thread constants (registers, no re-LDS)
    const float4 bi0 = s->bias0[hid];
    const float4 bi1 = s->bias1[hid];
    const float4 wx  = s->wx0[hid];

    float c00 = 0.0f, c01 = 0.0f;   // layer-0 cell state, 2 batches
    float c10 = 0.0f, c11 = 0.0f;   // layer-1 cell state, 2 batches

    float xa = x[xo0];
    float xb = x[xo1];

    const int h0off = pr * 2;

#pragma unroll 1
    for (int t = 0; t < TN; ++t) {
        const int rb = t & 1;        // read buffer (h^{t-1})
        const int wb = rb ^ 1;       // write buffer (h^{t})

        // ---- layer 0: gates = bias + Wih0*x_t + Whh0 @ h0 ----
        float4 A0, A1;
        A0.x = __fmaf_rn(wx.x, xa, bi0.x);
        A0.y = __fmaf_rn(wx.y, xa, bi0.y);
        A0.z = __fmaf_rn(wx.z, xa, bi0.z);
        A0.w = __fmaf_rn(wx.w, xa, bi0.w);
        A1.x = __fmaf_rn(wx.x, xb, bi0.x);
        A1.y = __fmaf_rn(wx.y, xb, bi0.y);
        A1.z = __fmaf_rn(wx.z, xb, bi0.z);
        A1.w = __fmaf_rn(wx.w, xb, bi0.w);

        // prefetch next x (consumed next iteration; latency fully hidden)
        const int tn = (t + 1 < TN) ? (t + 1) : (TN - 1);
        const float xan = x[xo0 + tn];
        const float xbn = x[xo1 + tn];

        {
            const float* h0r = &s->h0buf[rb][0][h0off];
#pragma unroll
            for (int k = 0; k < HN; ++k) {
                const float2 hp = *reinterpret_cast<const float2*>(h0r + k * NB);
                const float4 w = s->w0[k * HN + hid];
                A0.x += w.x * hp.x; A0.y += w.y * hp.x;
                A0.z += w.z * hp.x; A0.w += w.w * hp.x;
                A1.x += w.x * hp.y; A1.y += w.y * hp.y;
                A1.z += w.z * hp.y; A1.w += w.w * hp.y;
            }
        }
        float h0a, h0b;
        {
            const float i_ = sig_f(A0.x), f_ = sig_f(A0.y);
            const float g_ = tanh_f(A0.z), o_ = sig_f(A0.w);
            c00 = f_ * c00 + i_ * g_;
            h0a = o_ * tanh_f(c00);
        }
        {
            const float i_ = sig_f(A1.x), f_ = sig_f(A1.y);
            const float g_ = tanh_f(A1.z), o_ = sig_f(A1.w);
            c01 = f_ * c01 + i_ * g_;
            h0b = o_ * tanh_f(c01);
        }
        *reinterpret_cast<float2*>(&s->h0buf[wb][hid][h0off]) =
            make_float2(h0a, h0b);
        __syncthreads();

        // ---- layer 1: gates = bias + Wih1 @ h0_t + Whh1 @ h1 ----
        A0 = bi1;
        A1 = bi1;
        {
            const float* h0n = &s->h0buf[wb][0][h0off];
            const float* h1r = &s->h1buf[rb][0][h0off];
#pragma unroll
            for (int k = 0; k < HN; ++k) {
                const float2 hp = *reinterpret_cast<const float2*>(h0n + k * NB);
                const float2 hq = *reinterpret_cast<const float2*>(h1r + k * NB);
                const float4 wa = s->wi1[k * HN + hid];
                const float4 wr = s->w1 [k * HN + hid];
                A0.x += wa.x * hp.x + wr.x * hq.x;
                A0.y += wa.y * hp.x + wr.y * hq.x;
                A0.z += wa.z * hp.x + wr.z * hq.x;
                A0.w += wa.w * hp.x + wr.w * hq.x;
                A1.x += wa.x * hp.y + wr.x * hq.y;
                A1.y += wa.y * hp.y + wr.y * hq.y;
                A1.z += wa.z * hp.y + wr.z * hq.y;
                A1.w += wa.w * hp.y + wr.w * hq.y;
            }
        }
        float h1a, h1b;
        {
            const float i_ = sig_f(A0.x), f_ = sig_f(A0.y);
            const float g_ = tanh_f(A0.z), o_ = sig_f(A0.w);
            c10 = f_ * c10 + i_ * g_;
            h1a = o_ * tanh_f(c10);
        }
        {
            const float i_ = sig_f(A1.x), f_ = sig_f(A1.y);
            const float g_ = tanh_f(A1.z), o_ = sig_f(A1.w);
            c11 = f_ * c11 + i_ * g_;
            h1b = o_ * tanh_f(c11);
        }
        *reinterpret_cast<float2*>(&s->h1buf[wb][hid][h0off]) =
            make_float2(h1a, h1b);
        __syncthreads();

        xa = xan;
        xb = xbn;
    }

    // ---- final FC: out[b,c] = h1_last[b,:] . Wfc[c,:] + bfc[c] ----
    const int FB = TN & 1;   // buffer holding h1 at t = T-1  (= 0 for T=512)
    if (tid < NB * 2) {
        const int pb = tid >> 1;
        const int cc = tid & 1;
        const int b = blockIdx.x * NB + pb;
        if (b < BATCHN) {
            float acc = s->bfc2[cc];
#pragma unroll
            for (int k = 0; k < HN; ++k)
                acc += s->h1buf[FB][k][pb] * s->wfc[cc * HN + k];
            out[b * 2 + cc] = acc;
        }
    }
}

extern "C" void kernel_launch(void* const* d_in, const int* in_sizes, int n_in,
                              void* d_out, int out_size)
{
    (void)in_sizes; (void)n_in; (void)out_size;
    // Idempotent, no allocation; called every launch (deterministic).
    cudaFuncSetAttribute(lstm_fused_kernel,
                         cudaFuncAttributeMaxDynamicSharedMemorySize,
                         (int)sizeof(Smem));

    lstm_fused_kernel<<<NGRID, NTHREADS, sizeof(Smem)>>>(
        (const float*)d_in[0],   // x
        (const float*)d_in[1],   // W_ih0
        (const float*)d_in[2],   // W_hh0
        (const float*)d_in[3],   // b_ih0
        (const float*)d_in[4],   // b_hh0
        (const float*)d_in[5],   // W_ih1
        (const float*)d_in[6],   // W_hh1
        (const float*)d_in[7],   // b_ih1
        (const float*)d_in[8],   // b_hh1
        (const float*)d_in[9],   // W_fc
        (const float*)d_in[10],  // b_fc
        (float*)d_out);
}

// round 5
// speedup vs baseline: 1.0586x; 1.0586x over previous
#include <cuda_runtime.h>

// ---------------------------------------------------------------------------
// Fused 2-layer LSTM (H=50, D=1) + final FC, batch=2048, T=512, fp32.
//
// Parallelization: batch is fully independent -> persistent blocks, one per
// SM (grid=147). Each block owns 14 batches and runs the whole T=512 loop
// with only __syncthreads() between the per-step layer stages. Each thread
// owns one (batch-pair, hidden-unit): computes the 4 gate rows for its
// hidden unit for 2 batches, keeping cell state c in registers.
//
// Weights live in shared memory in a gate-interleaved float4 layout
// W[k][hid] = {w_i, w_f, w_g, w_o} so the inner dot loop is:
//     1x LDS.128 (weights) + 1x LDS.64 (h pair) + 8x FFMA   per k.
// ---------------------------------------------------------------------------

#define HN      50
#define TN      512
#define BATCHN  2048
#define NB      14          // batches per block
#define NPAIR   7           // batch pairs per block
#define NTHREADS (NPAIR * HN)   // 350
#define NGRID   ((BATCHN + NB - 1) / NB)   // 147

struct Smem {
    float4 w0 [HN * HN];   // [k][hid] gates of W_hh0
    float4 wi1[HN * HN];   // [k][hid] gates of W_ih1
    float4 w1 [HN * HN];   // [k][hid] gates of W_hh1
    float4 bias0[HN];      // b_ih0 + b_hh0, per gate
    float4 bias1[HN];      // b_ih1 + b_hh1, per gate
    float4 wx0[HN];        // W_ih0[:,0], per gate (D == 1)
    float  h0buf[2][HN][NB];
    float  h1buf[2][HN][NB];
    float  wfc[2 * HN];
    float  bfc2[2];
};

__device__ __forceinline__ float sig_f(float v) {
    return __fdividef(1.0f, 1.0f + __expf(-v));
}
__device__ __forceinline__ float tanh_f(float v) {
    // 1 - 2/(1+e^{2v}); __fdividef(2, inf) -> 0 so large |v| saturates cleanly
    return 1.0f - __fdividef(2.0f, 1.0f + __expf(2.0f * v));
}

__global__ __launch_bounds__(NTHREADS, 1)
void lstm_fused_kernel(const float* __restrict__ x,      // [B,T,1]
                       const float* __restrict__ Wih0,   // [200,1]
                       const float* __restrict__ Whh0,   // [200,50]
                       const float* __restrict__ bih0,   // [200]
                       const float* __restrict__ bhh0,   // [200]
                       const float* __restrict__ Wih1,   // [200,50]
                       const float* __restrict__ Whh1,   // [200,50]
                       const float* __restrict__ bih1,   // [200]
                       const float* __restrict__ bhh1,   // [200]
                       const float* __restrict__ Wfc,    // [2,50]
                       const float* __restrict__ bfc,    // [2]
                       float* __restrict__ out)          // [B,2]
{
    extern __shared__ char smem_raw[];
    Smem* s = reinterpret_cast<Smem*>(smem_raw);
    const int tid = threadIdx.x;

    // ---------------- stage weights into shared (once per block) ----------
    for (int idx = tid; idx < HN * HN; idx += NTHREADS) {
        const int k = idx / HN, hid = idx % HN;
        s->w0[idx] = make_float4(Whh0[(0 * HN + hid) * HN + k],
                                 Whh0[(1 * HN + hid) * HN + k],
                                 Whh0[(2 * HN + hid) * HN + k],
                                 Whh0[(3 * HN + hid) * HN + k]);
        s->wi1[idx] = make_float4(Wih1[(0 * HN + hid) * HN + k],
                                  Wih1[(1 * HN + hid) * HN + k],
                                  Wih1[(2 * HN + hid) * HN + k],
                                  Wih1[(3 * HN + hid) * HN + k]);
        s->w1[idx] = make_float4(Whh1[(0 * HN + hid) * HN + k],
                                 Whh1[(1 * HN + hid) * HN + k],
                                 Whh1[(2 * HN + hid) * HN + k],
                                 Whh1[(3 * HN + hid) * HN + k]);
    }
    for (int hid = tid; hid < HN; hid += NTHREADS) {
        s->bias0[hid] = make_float4(bih0[0 * HN + hid] + bhh0[0 * HN + hid],
                                    bih0[1 * HN + hid] + bhh0[1 * HN + hid],
                                    bih0[2 * HN + hid] + bhh0[2 * HN + hid],
                                    bih0[3 * HN + hid] + bhh0[3 * HN + hid]);
        s->bias1[hid] = make_float4(bih1[0 * HN + hid] + bhh1[0 * HN + hid],
                                    bih1[1 * HN + hid] + bhh1[1 * HN + hid],
                                    bih1[2 * HN + hid] + bhh1[2 * HN + hid],
                                    bih1[3 * HN + hid] + bhh1[3 * HN + hid]);
        s->wx0[hid] = make_float4(Wih0[0 * HN + hid], Wih0[1 * HN + hid],
                                  Wih0[2 * HN + hid], Wih0[3 * HN + hid]);
    }
    for (int i = tid; i < 2 * HN; i += NTHREADS) s->wfc[i] = Wfc[i];
    if (tid < 2) s->bfc2[tid] = bfc[tid];
    // zero initial hidden state (buffer 0 is read at t=0)
    for (int i = tid; i < HN * NB; i += NTHREADS) {
        (&s->h0buf[0][0][0])[i] = 0.0f;
        (&s->h1buf[0][0][0])[i] = 0.0f;
    }
    __syncthreads();

    // ---------------- per-thread identity ---------------------------------
    const int hid = tid / NPAIR;       // hidden unit owned by this thread
    const int pr  = tid % NPAIR;       // batch pair within block
    const int b0  = blockIdx.x * NB + pr * 2;
    const int b1  = b0 + 1;
    const long xo0 = (long)(b0 < BATCHN ? b0 : BATCHN - 1) * TN;
    const long xo1 = (long)(b1 < BATCHN ? b1 : BATCHN - 1) * TN;

    // loop-invariant per-thread constants (registers, no re-LDS)
    const float4 bi0 = s->bias0[hid];
    const float4 bi1 = s->bias1[hid];
    const float4 wx  = s->wx0[hid];

    float c00 = 0.0f, c01 = 0.0f;   // layer-0 cell state, 2 batches
    float c10 = 0.0f, c11 = 0.0f;   // layer-1 cell state, 2 batches

    float xa = x[xo0];
    float xb = x[xo1];

    const int h0off = pr * 2;

#pragma unroll 1
    for (int t = 0; t < TN; ++t) {
        const int rb = t & 1;        // read buffer (h^{t-1})
        const int wb = rb ^ 1;       // write buffer (h^{t})

        // ---- layer 0: gates = bias + Wih0*x_t + Whh0 @ h0 ----
        float4 A0, A1;
        A0.x = __fmaf_rn(wx.x, xa, bi0.x);
        A0.y = __fmaf_rn(wx.y, xa, bi0.y);
        A0.z = __fmaf_rn(wx.z, xa, bi0.z);
        A0.w = __fmaf_rn(wx.w, xa, bi0.w);
        A1.x = __fmaf_rn(wx.x, xb, bi0.x);
        A1.y = __fmaf_rn(wx.y, xb, bi0.y);
        A1.z = __fmaf_rn(wx.z, xb, bi0.z);
        A1.w = __fmaf_rn(wx.w, xb, bi0.w);

        // prefetch next x (consumed next iteration; latency fully hidden)
        const int tn = (t + 1 < TN) ? (t + 1) : (TN - 1);
        const float xan = x[xo0 + tn];
        const float xbn = x[xo1 + tn];

        {
            const float* h0r = &s->h0buf[rb][0][h0off];
#pragma unroll
            for (int k = 0; k < HN; ++k) {
                const float2 hp = *reinterpret_cast<const float2*>(h0r + k * NB);
                const float4 w = s->w0[k * HN + hid];
                A0.x += w.x * hp.x; A0.y += w.y * hp.x;
                A0.z += w.z * hp.x; A0.w += w.w * hp.x;
                A1.x += w.x * hp.y; A1.y += w.y * hp.y;
                A1.z += w.z * hp.y; A1.w += w.w * hp.y;
            }
        }
        float h0a, h0b;
        {
            const float i_ = sig_f(A0.x), f_ = sig_f(A0.y);
            const float g_ = tanh_f(A0.z), o_ = sig_f(A0.w);
            c00 = f_ * c00 + i_ * g_;
            h0a = o_ * tanh_f(c00);
        }
        {
            const float i_ = sig_f(A1.x), f_ = sig_f(A1.y);
            const float g_ = tanh_f(A1.z), o_ = sig_f(A1.w);
            c01 = f_ * c01 + i_ * g_;
            h0b = o_ * tanh_f(c01);
        }
        *reinterpret_cast<float2*>(&s->h0buf[wb][hid][h0off]) =
            make_float2(h0a, h0b);
        __syncthreads();

        // ---- layer 1: gates = bias + Wih1 @ h0_t + Whh1 @ h1 ----
        A0 = bi1;
        A1 = bi1;
        {
            const float* h0n = &s->h0buf[wb][0][h0off];
            const float* h1r = &s->h1buf[rb][0][h0off];
#pragma unroll
            for (int k = 0; k < HN; ++k) {
                const float2 hp = *reinterpret_cast<const float2*>(h0n + k * NB);
                const float2 hq = *reinterpret_cast<const float2*>(h1r + k * NB);
                const float4 wa = s->wi1[k * HN + hid];
                const float4 wr = s->w1 [k * HN + hid];
                A0.x += wa.x * hp.x + wr.x * hq.x;
                A0.y += wa.y * hp.x + wr.y * hq.x;
                A0.z += wa.z * hp.x + wr.z * hq.x;
                A0.w += wa.w * hp.x + wr.w * hq.x;
                A1.x += wa.x * hp.y + wr.x * hq.y;
                A1.y += wa.y * hp.y + wr.y * hq.y;
                A1.z += wa.z * hp.y + wr.z * hq.y;
                A1.w += wa.w * hp.y + wr.w * hq.y;
            }
        }
        float h1a, h1b;
        {
            const float i_ = sig_f(A0.x), f_ = sig_f(A0.y);
            const float g_ = tanh_f(A0.z), o_ = sig_f(A0.w);
            c10 = f_ * c10 + i_ * g_;
            h1a = o_ * tanh_f(c10);
        }
        {
            const float i_ = sig_f(A1.x), f_ = sig_f(A1.y);
            const float g_ = tanh_f(A1.z), o_ = sig_f(A1.w);
            c11 = f_ * c11 + i_ * g_;
            h1b = o_ * tanh_f(c11);
        }
        *reinterpret_cast<float2*>(&s->h1buf[wb][hid][h0off]) =
            make_float2(h1a, h1b);
        __syncthreads();

        xa = xan;
        xb = xbn;
    }

    // ---- final FC: out[b,c] = h1_last[b,:] . Wfc[c,:] + bfc[c] ----
    const int FB = TN & 1;   // buffer holding h1 at t = T-1  (= 0 for T=512)
    if (tid < NB * 2) {
        const int pb = tid >> 1;
        const int cc = tid & 1;
        const int b = blockIdx.x * NB + pb;
        if (b < BATCHN) {
            float acc = s->bfc2[cc];
#pragma unroll
            for (int k = 0; k < HN; ++k)
                acc += s->h1buf[FB][k][pb] * s->wfc[cc * HN + k];
            out[b * 2 + cc] = acc;
        }
    }
}

extern "C" void kernel_launch(void* const* d_in, const int* in_sizes, int n_in,
                              void* d_out, int out_size)
{
    (void)in_sizes; (void)n_in; (void)out_size;
    // Idempotent, no allocation; called every launch (deterministic).
    cudaFuncSetAttribute(lstm_fused_kernel,
                         cudaFuncAttributeMaxDynamicSharedMemorySize,
                         (int)sizeof(Smem));

    lstm_fused_kernel<<<NGRID, NTHREADS, sizeof(Smem)>>>(
        (const float*)d_in[0],   // x
        (const float*)d_in[1],   // W_ih0
        (const float*)d_in[2],   // W_hh0
        (const float*)d_in[3],   // b_ih0
        (const float*)d_in[4],   // b_hh0
        (const float*)d_in[5],   // W_ih1
        (const float*)d_in[6],   // W_hh1
        (const float*)d_in[7],   // b_ih1
        (const float*)d_in[8],   // b_hh1
        (const float*)d_in[9],   // W_fc
        (const float*)d_in[10],  // b_fc
        (float*)d_out);
}